// round 10
// baseline (speedup 1.0000x reference)
#include <cuda_runtime.h>
#include <math.h>
#include <stdint.h>

#define BATCH     16
#define MEM_DIM   172
#define KPAD      176
#define TOK       4096
#define TIME_DIM  100
#define TPAD      112
#define LEN_TOK   512
#define NROWS     44
#define ASTRIDE   24
#define NGROUPS   4
#define GBATCH    (BATCH / NGROUPS)

typedef unsigned long long ull;

__device__ __align__(16) float g_res[BATCH * NROWS * TOK];

__device__ __forceinline__ ull pack2(float lo, float hi) {
    ull d; asm("mov.b64 %0, {%1, %2};" : "=l"(d) : "f"(lo), "f"(hi)); return d;
}
__device__ __forceinline__ void unpack2(ull v, float& lo, float& hi) {
    asm("mov.b64 {%0, %1}, %2;" : "=f"(lo), "=f"(hi) : "l"(v));
}
__device__ __forceinline__ ull fma2(ull a, ull b, ull c) {
    ull d; asm("fma.rn.f32x2 %0, %1, %2, %3;" : "=l"(d) : "l"(a), "l"(b), "l"(c)); return d;
}
__device__ __forceinline__ ull add2(ull a, ull b) {
    ull d; asm("add.rn.f32x2 %0, %1, %2;" : "=l"(d) : "l"(a), "l"(b)); return d;
}
__device__ __forceinline__ uint32_t s2u(const void* p) {
    return (uint32_t)__cvta_generic_to_shared(p);
}
__device__ __forceinline__ void cp16(uint32_t dst, const void* src) {
    asm volatile("cp.async.cg.shared.global [%0], [%1], 16;" :: "r"(dst), "l"(src));
}
__device__ __forceinline__ void cp_commit() { asm volatile("cp.async.commit_group;"); }
template<int N> __device__ __forceinline__ void cp_wait() {
    asm volatile("cp.async.wait_group %0;" :: "n"(N) : "memory");
}

__device__ __forceinline__ void fill_w(float* buf, const float* W1, const float* W2,
                                       int kbase, int colbase, int cl)
{
#pragma unroll
    for (int j = 0; j < 4; j++) {
        int c   = cl + 128 * j;
        int mat = c >> 8;
        int k   = (c >> 5) & 7;
        int c16 = c & 31;
        int krow = kbase + k; if (krow > MEM_DIM - 1) krow = MEM_DIM - 1;
        const float* src = (mat ? W2 : W1) + (size_t)krow * TOK + colbase + c16 * 4;
        cp16(s2u(buf + k * 256 + mat * 128 + c16 * 4), src);
    }
}

__device__ __forceinline__ void fill_t(float* buf, const float* Wt,
                                       int kbase, int colbase, int cl)
{
#pragma unroll
    for (int j = 0; j < 2; j++) {
        int c   = cl + 128 * j;
        int k   = c >> 5;
        int c16 = c & 31;
        int krow = kbase + k; if (krow > TIME_DIM - 1) krow = TIME_DIM - 1;
        cp16(s2u(buf + k * 128 + c16 * 4), Wt + (size_t)krow * TOK + colbase + c16 * 4);
    }
}

#define ASH_B  (KPAD * ASTRIDE * 4)
#define WB_B   (2 * 2 * 8 * 256 * 4)
#define SMEM_B (ASH_B + WB_B)            // 49664 B

// ---------------------------------------------------------------------------
// Kernel A: projections for GBATCH batches. grid (GBATCH, 32 tiles of 128),
// block 256 = 128 cols x 2 k-slices. cp.async double-buffered W stream.
// ---------------------------------------------------------------------------
__global__ void __launch_bounds__(256, 4)
k_proj(const float* __restrict__ memory,
       const int*   __restrict__ src_nodes,
       const int*   __restrict__ dst_nodes,
       const int*   __restrict__ src_nei,
       const int*   __restrict__ dst_nei,
       const float* __restrict__ timestamps,
       const float* __restrict__ se,
       const float* __restrict__ de,
       const float* __restrict__ W1, const float* __restrict__ b1,
       const float* __restrict__ W2, const float* __restrict__ b2,
       const float* __restrict__ Wt, const float* __restrict__ bt,
       const float* __restrict__ w_time,
       const float* __restrict__ phase,
       int b0)
{
    extern __shared__ __align__(16) char sraw[];
    float* Ash = (float*)sraw;
    float* Wb  = (float*)(sraw + ASH_B);
    float* Ten = Wb;
    float* Tw  = Wb + TPAD * ASTRIDE;
    ull*   red = (ull*)sraw;

    const int b       = b0 + blockIdx.x;
    const int tile    = blockIdx.y;
    const int tid     = threadIdx.x;
    const int cl      = tid & 127;
    const int slice   = tid >> 7;
    const int col     = tile * 128 + cl;
    const int colbase = tile * 128;

    const int kb0 = slice ? 88 : 0;
    float* mbuf = Wb + slice * 4096;
    fill_w(mbuf, W1, W2, kb0, colbase, cl);
    cp_commit();

    for (int i = tid; i < 22 * MEM_DIM; i += 256) {
        int r = i / MEM_DIM;
        int k = i - r * MEM_DIM;
        int node;
        if (r == 0)       node = src_nodes[b];
        else if (r < 11)  node = dst_nei[b * 10 + r - 1];
        else if (r == 11) node = dst_nodes[b];
        else              node = src_nei[b * 10 + r - 12];
        int slot = (r < 11) ? (2 * r) : (2 * (r - 11) + 1);
        Ash[k * ASTRIDE + slot] = memory[(size_t)node * MEM_DIM + k];
    }
    if (tid < (KPAD - MEM_DIM) * ASTRIDE)
        Ash[MEM_DIM * ASTRIDE + tid] = 0.f;
    __syncthreads();

    float* resb = g_res + (size_t)b * NROWS * TOK + col;

    // ---- mem projection ----
    {
        ull acc[11];
        const ull bi = pack2(b1[col], b2[col]);
#pragma unroll
        for (int p = 0; p < 11; p++) acc[p] = slice == 0 ? bi : 0ull;

        for (int s = 0; s < 11; s++) {
            if (s + 1 < 11) {
                fill_w(mbuf + ((s + 1) & 1) * 2048, W1, W2, kb0 + (s + 1) * 8, colbase, cl);
                cp_commit();
                cp_wait<1>();
            } else {
                cp_wait<0>();
            }
            __syncthreads();

            const float* bufc = mbuf + (s & 1) * 2048;
            const int kb = kb0 + s * 8;
#pragma unroll
            for (int j = 0; j < 8; j++) {
                ull w = pack2(bufc[j * 256 + cl], bufc[j * 256 + 128 + cl]);
                const float* a = Ash + (kb + j) * ASTRIDE;
#pragma unroll
                for (int q = 0; q < 5; q++) {
                    ulonglong2 v = *(const ulonglong2*)(a + 4 * q);
                    acc[2 * q]     = fma2(v.x, w, acc[2 * q]);
                    acc[2 * q + 1] = fma2(v.y, w, acc[2 * q + 1]);
                }
                acc[10] = fma2(*(const ull*)(a + 20), w, acc[10]);
            }
            __syncthreads();
        }

        const int tb0 = slice ? 56 : 0;
        fill_t(Tw + slice * 2048, Wt, tb0, colbase, cl);
        cp_commit();

        if (slice) {
#pragma unroll
            for (int p = 0; p < 11; p++) red[cl * 11 + p] = acc[p];
        }
        __syncthreads();
        if (slice == 0) {
#pragma unroll
            for (int p = 0; p < 11; p++) {
                acc[p] = add2(acc[p], red[cl * 11 + p]);
                float lo, hi; unpack2(acc[p], lo, hi);
                resb[(size_t)p * TOK]        = lo;
                resb[(size_t)(11 + p) * TOK] = hi;
            }
        }
    }
    __syncthreads();

    // ---- stage Ten ----
    const float t0v = timestamps[b];
    for (int i = tid; i < TPAD * ASTRIDE; i += 256) {
        int k = i / ASTRIDE;
        int r = i - k * ASTRIDE;
        float v = 0.f;
        if (k < TIME_DIM && r < 21) {
            float delta;
            if (r == 0)      delta = 0.f;
            else if (r < 11) delta = t0v - se[b * 10 + r - 1];
            else             delta = t0v - de[b * 10 + r - 11];
            v = cosf(delta * w_time[k] + phase[k]);
        }
        Ten[i] = v;
    }
    __syncthreads();

    // ---- time projection ----
    {
        const int tb0 = slice ? 56 : 0;
        float* tbuf = Tw + slice * 2048;

        ull acc[11];
        const float btc = bt[col];
        const ull bi = pack2(btc, btc);
#pragma unroll
        for (int p = 0; p < 11; p++) acc[p] = slice == 0 ? bi : 0ull;

        for (int s = 0; s < 7; s++) {
            if (s + 1 < 7) {
                fill_t(tbuf + ((s + 1) & 1) * 1024, Wt, tb0 + (s + 1) * 8, colbase, cl);
                cp_commit();
                cp_wait<1>();
            } else {
                cp_wait<0>();
            }
            __syncthreads();

            const float* bufc = tbuf + (s & 1) * 1024;
            const int kb = tb0 + s * 8;
#pragma unroll
            for (int j = 0; j < 8; j++) {
                float wt = bufc[j * 128 + cl];
                ull w = pack2(wt, wt);
                const float* a = Ten + (kb + j) * ASTRIDE;
#pragma unroll
                for (int q = 0; q < 5; q++) {
                    ulonglong2 v = *(const ulonglong2*)(a + 4 * q);
                    acc[2 * q]     = fma2(v.x, w, acc[2 * q]);
                    acc[2 * q + 1] = fma2(v.y, w, acc[2 * q + 1]);
                }
                acc[10] = fma2(*(const ull*)(a + 20), w, acc[10]);
            }
            __syncthreads();
        }

        if (slice) {
#pragma unroll
            for (int p = 0; p < 11; p++) red[cl * 11 + p] = acc[p];
        }
        __syncthreads();
        if (slice == 0) {
#pragma unroll
            for (int p = 0; p < 11; p++) {
                acc[p] = add2(acc[p], red[cl * 11 + p]);
                float lo, hi; unpack2(acc[p], lo, hi);
                resb[(size_t)(22 + 2 * p) * TOK] = lo;
                resb[(size_t)(23 + 2 * p) * TOK] = hi;
            }
        }
    }
}

// ---------------------------------------------------------------------------
// Kernel B: run-grouped scatter for GBATCH batches.
// grid (GBATCH, 16 tiles of 256 cols, 25 runs), block 256. No smem/barriers.
// ---------------------------------------------------------------------------
__global__ void __launch_bounds__(256)
k_scat(float* __restrict__ out, int b0)
{
    const int b    = b0 + blockIdx.x;
    const int tile = blockIdx.y;
    const int z    = blockIdx.z;
    const int tid  = threadIdx.x;
    const int lane = tid & 63;
    const int sub  = tid >> 6;

    int t0, n, rS, rD, rT;
    if (z < 10)       { t0 = 15 + 21 * z;  n = 21; rS = 0;  rD = 12 + z; rT = 23 + z; }
    else if (z < 20)  { int q = z - 10; t0 = 239 + 21 * q; n = 21; rS = 11; rD = 1 + q; rT = 33 + q; }
    else if (z == 20) { t0 = 0;   n = 15; rS = 0;  rD = 11; rT = 22; }
    else if (z == 21) { t0 = 225; n = 14; rS = 11; rD = 11; rT = 22; }
    else              { t0 = 449 + 21 * (z - 22); n = 21; rS = 0; rD = 11; rT = 22; }

    const float4* gresv = (const float4*)g_res;
    const int vrow = TOK / 4;
    const size_t rbase = (size_t)b * NROWS * vrow + tile * 64 + lane;
    const float4 vs = __ldg(&gresv[rbase + (size_t)rS * vrow]);
    const float4 vd = __ldg(&gresv[rbase + (size_t)rD * vrow]);
    const float4 vt = __ldg(&gresv[rbase + (size_t)rT * vrow]);

    float4* outv = (float4*)out;
    const size_t T = (size_t)BATCH * LEN_TOK * vrow;
    const size_t obase = (size_t)(b * LEN_TOK) * vrow + tile * 64 + lane;

    if (z == 20) {
        for (int i = sub; i < n; i += 4) {
            const int t = t0 + i;
            const size_t o = obase + (size_t)t * vrow;
            __stcs(&outv[o],         vs);
            __stcs(&outv[o + T],     (t == 0) ? vd : vs);
            __stcs(&outv[o + 2 * T], vt);
        }
    } else {
        for (int i = sub; i < n; i += 4) {
            const size_t o = obase + (size_t)(t0 + i) * vrow;
            __stcs(&outv[o],         vs);
            __stcs(&outv[o + T],     vd);
            __stcs(&outv[o + 2 * T], vt);
        }
    }
}

// ---------------------------------------------------------------------------
// 4-group pipeline: proj(g) on capture stream, scat(g) on side stream gated by
// event; scat(g) overlaps proj(g+1). Final join back on capture stream.
// ---------------------------------------------------------------------------
extern "C" void kernel_launch(void* const* d_in, const int* in_sizes, int n_in,
                              void* d_out, int out_size)
{
    const float* memory      = (const float*)d_in[0];
    const int*   src_nodes   = (const int*)  d_in[1];
    const int*   dst_nodes   = (const int*)  d_in[2];
    const int*   src_nei     = (const int*)  d_in[3];
    const int*   dst_nei     = (const int*)  d_in[4];
    const float* timestamps  = (const float*)d_in[5];
    const float* se          = (const float*)d_in[6];
    const float* de          = (const float*)d_in[7];
    const float* W1          = (const float*)d_in[8];
    const float* b1          = (const float*)d_in[9];
    const float* W2          = (const float*)d_in[10];
    const float* b2          = (const float*)d_in[11];
    const float* Wt          = (const float*)d_in[12];
    const float* bt          = (const float*)d_in[13];
    const float* w_time      = (const float*)d_in[14];
    const float* phase       = (const float*)d_in[15];
    float* out = (float*)d_out;

    static cudaStream_t s1 = nullptr;
    static cudaEvent_t  ep[NGROUPS];
    static cudaEvent_t  ej;
    if (s1 == nullptr) {
        cudaStreamCreateWithFlags(&s1, cudaStreamNonBlocking);
        for (int g = 0; g < NGROUPS; g++)
            cudaEventCreateWithFlags(&ep[g], cudaEventDisableTiming);
        cudaEventCreateWithFlags(&ej, cudaEventDisableTiming);
        cudaFuncSetAttribute(k_proj, cudaFuncAttributeMaxDynamicSharedMemorySize, SMEM_B);
    }

    for (int g = 0; g < NGROUPS; g++) {
        k_proj<<<dim3(GBATCH, TOK / 128), 256, SMEM_B>>>(memory, src_nodes, dst_nodes,
                                                         src_nei, dst_nei,
                                                         timestamps, se, de,
                                                         W1, b1, W2, b2, Wt, bt,
                                                         w_time, phase, g * GBATCH);
        cudaEventRecord(ep[g], 0);
        cudaStreamWaitEvent(s1, ep[g], 0);
        k_scat<<<dim3(GBATCH, TOK / 256, 25), 256, 0, s1>>>(out, g * GBATCH);
    }
    cudaEventRecord(ej, s1);
    cudaStreamWaitEvent(0, ej, 0);
}